// round 15
// baseline (speedup 1.0000x reference)
#include <cuda_runtime.h>
#include <cuda_fp16.h>
#include <cstdint>
#include <math.h>

// ---------------------------------------------------------------------------
// ChunkedAttention: B=8, C=1024, L=4096, H=8, hd=128, CHUNK=64, nc=64
// Round 15: convert_x FUSED into QKV GEMM (fp32 x-tiles cp.async'd, converted
// to fp16 A-panels in-loop, interleaved with MMAs). Out-proj reverted to R13
// direct-store epilogue. Numerics identical to R13 (bit-exact rel_err).
// ---------------------------------------------------------------------------

#define BDIM 8
#define CDIM 1024
#define LDIM 4096
#define HEADS 8
#define HD 128
#define CHUNK 64
#define NCHUNK (LDIM / CHUNK)
#define MTOT (BDIM * LDIM)          // 32768 rows

__device__ __half g_Qh[(size_t)MTOT * CDIM];
__device__ __half g_Kh[(size_t)MTOT * CDIM];
__device__ __half g_Vh[(size_t)MTOT * CDIM];
__device__ __half g_Af[(size_t)MTOT * CDIM];            // attn out (oproj A)
__device__ __half g_Wf[(size_t)4 * CDIM * CDIM];        // [mat][co][c] fp16

// ------------------------------ PTX helpers --------------------------------
__device__ __forceinline__ uint32_t smem_u32(const void* p) {
    uint32_t a;
    asm("{ .reg .u64 t; cvta.to.shared.u64 t, %1; cvt.u32.u64 %0, t; }"
        : "=r"(a) : "l"(p));
    return a;
}
#define CP_ASYNC16(dst, src) \
    asm volatile("cp.async.cg.shared.global [%0], [%1], 16;" :: "r"(dst), "l"(src))
#define CP_COMMIT() asm volatile("cp.async.commit_group;" ::: "memory")
#define CP_WAIT(n)  asm volatile("cp.async.wait_group %0;" :: "n"(n) : "memory")
#define SW128(off) ((off) ^ (((off) >> 3) & 0x70))

__device__ __forceinline__ void ldsm4(uint32_t& r0, uint32_t& r1,
                                      uint32_t& r2, uint32_t& r3, uint32_t a) {
    asm volatile("ldmatrix.sync.aligned.m8n8.x4.shared.b16 {%0,%1,%2,%3}, [%4];"
                 : "=r"(r0), "=r"(r1), "=r"(r2), "=r"(r3) : "r"(a));
}
__device__ __forceinline__ void ldsm4t(uint32_t& r0, uint32_t& r1,
                                       uint32_t& r2, uint32_t& r3, uint32_t a) {
    asm volatile("ldmatrix.sync.aligned.m8n8.x4.trans.shared.b16 {%0,%1,%2,%3}, [%4];"
                 : "=r"(r0), "=r"(r1), "=r"(r2), "=r"(r3) : "r"(a));
}
__device__ __forceinline__ void mma16816(float* c, const uint32_t* a,
                                         const uint32_t* b) {
    asm volatile(
        "mma.sync.aligned.m16n8k16.row.col.f32.f16.f16.f32 "
        "{%0,%1,%2,%3}, {%4,%5,%6,%7}, {%8,%9}, {%0,%1,%2,%3};"
        : "+f"(c[0]), "+f"(c[1]), "+f"(c[2]), "+f"(c[3])
        : "r"(a[0]), "r"(a[1]), "r"(a[2]), "r"(a[3]), "r"(b[0]), "r"(b[1]));
}
__device__ __forceinline__ uint32_t packh2(float x, float y) {
    __half2 h = __floats2half2_rn(x, y);
    return *(uint32_t*)&h;
}

// ---------------------------------------------------------------------------
// convert_w (unchanged): W [C,C] ([c,co]) -> Wt fp16 [co,c] at slot z
// ---------------------------------------------------------------------------
__global__ void convert_w(const float* __restrict__ W0, const float* __restrict__ W1,
                          const float* __restrict__ W2, const float* __restrict__ W3,
                          __half* __restrict__ Wf) {
    __shared__ float t[32][33];
    const int z = blockIdx.z;
    const float* W = (z == 0) ? W0 : (z == 1) ? W1 : (z == 2) ? W2 : W3;
    const int c0 = blockIdx.x * 32, n0 = blockIdx.y * 32;
#pragma unroll
    for (int i = 0; i < 32; i += 8)
        t[threadIdx.y + i][threadIdx.x] = W[(size_t)(c0 + threadIdx.y + i) * CDIM + n0 + threadIdx.x];
    __syncthreads();
#pragma unroll
    for (int i = 0; i < 32; i += 8) {
        const int r = threadIdx.y + i;
        size_t o = ((size_t)z * CDIM + n0 + r) * CDIM + c0 + threadIdx.x;
        Wf[o] = __float2half(t[threadIdx.x][r]);
    }
}

// ---------------------------------------------------------------------------
// Fused QKV GEMM: Y[m,n] = sum_k fp16(x[b][k][l]) * Wt[n,k] + bias[n]
// A-side comes straight from x (fp32, [B][C][L]): per chunk a 64(k)x128(l)
// fp32 tile is cp.async'd (132-float padded rows), then converted to the
// fp16 A-panel [l][k] (SW128, identical ldsm addressing as before), one
// quarter per ks-step, one chunk ahead of the MMAs.
// smem: xbuf x2 (33792B) | Apanel x2 (16384B) | W x3 (32768B) = 198656B
// ---------------------------------------------------------------------------
#define XBUF_B 33792
#define APAN_OFF (2 * XBUF_B)                  // 67584 (1024-aligned)
#define WBUF_OFF (APAN_OFF + 2 * 16384)        // 100352 (1024-aligned)
#define QKV_SMEM (WBUF_OFF + 3 * 32768)        // 198656

__device__ __forceinline__ void convert_quarter(uint32_t xb, uint32_t ap,
                                                int tid, int q) {
    const int l = tid & 127;
    const int kh = (tid >> 7) << 3;            // 0 or 8
#pragma unroll
    for (int j = 0; j < 4; j++) {
        const int kr = q * 16 + kh + 2 * j;
        float v0, v1;
        asm("ld.shared.f32 %0, [%1];" : "=f"(v0)
            : "r"(xb + (uint32_t)((kr * 132 + l) * 4)));
        asm("ld.shared.f32 %0, [%1];" : "=f"(v1)
            : "r"(xb + (uint32_t)(((kr + 1) * 132 + l) * 4)));
        const uint32_t h2 = packh2(v0, v1);
        asm volatile("st.shared.b32 [%0], %1;"
                     :: "r"(ap + SW128((uint32_t)(l * 128 + kr * 2))), "r"(h2));
    }
}

__global__ __launch_bounds__(256, 1)
void gemm_qkv(const float* __restrict__ x, const __half* __restrict__ Wf,
              const float* __restrict__ bq, const float* __restrict__ bk,
              const float* __restrict__ bv,
              __half* __restrict__ Yq, __half* __restrict__ Yk,
              __half* __restrict__ Yv)
{
    extern __shared__ char smem[];
    const uint32_t sb = smem_u32(smem);
    const int tid = threadIdx.x;
    const int wid = tid >> 5, lane = tid & 31;
    const int m0 = blockIdx.y * 128;
    const int nt_blk = blockIdx.x;             // 0..11 (fast axis, L2 reuse)

    const int mat = nt_blk >> 2;
    const int ncol0 = (nt_blk & 3) * 256;
    const float* bias = (mat == 0) ? bq : (mat == 1) ? bk : bv;
    __half* Y = (mat == 0) ? Yq : (mat == 1) ? Yk : Yv;

    const __half* Bw = Wf + ((size_t)mat * CDIM + ncol0) * CDIM;
    const int bb = m0 >> 12;                   // batch (128 rows within one b)
    const int l0 = m0 & (LDIM - 1);
    const float* xg = x + (size_t)bb * CDIM * LDIM + l0;

    const int warp_m = (wid & 1) * 64;
    const int warp_n = (wid >> 1) * 64;

    float acc[4][8][4];
#pragma unroll
    for (int i = 0; i < 4; i++)
#pragma unroll
        for (int j = 0; j < 8; j++)
#pragma unroll
            for (int r = 0; r < 4; r++) acc[i][j][r] = 0.0f;

    auto load_stage = [&](int chunk) {
        const int kk = chunk * 64;
        // x fp32 tile: 64 rows x 32 chunks of 16B, padded rows (528B)
        const uint32_t xs = sb + (chunk & 1) * XBUF_B;
#pragma unroll
        for (int i = 0; i < 8; i++) {
            const int idx = tid + i * 256;     // 0..2047
            const int r = idx >> 5, c16 = idx & 31;
            CP_ASYNC16(xs + (uint32_t)(r * 528 + c16 * 16),
                       xg + (size_t)(kk + r) * LDIM + c16 * 4);
        }
        // W fp16 tile: 256 rows x 8 chunks of 16B, SW128
        const uint32_t ws = sb + WBUF_OFF + (chunk % 3) * 32768;
#pragma unroll
        for (int i = 0; i < 8; i++) {
            const int idx = tid + i * 256;
            const int r = idx >> 3, cc = idx & 7;
            CP_ASYNC16(ws + SW128((uint32_t)(r * 128 + cc * 16)),
                       (const char*)(Bw + (size_t)r * CDIM + kk) + cc * 16);
        }
        CP_COMMIT();
    };

    load_stage(0);
    load_stage(1);

    CP_WAIT(1);                                // x(0), W(0) arrived
    __syncthreads();
    {
        const uint32_t xs0 = sb;
        const uint32_t ap0 = sb + APAN_OFF;
#pragma unroll
        for (int q = 0; q < 4; q++) convert_quarter(xs0, ap0, tid, q);
    }

    const int a_row = warp_m + (lane & 15);
    const int a_colx = (lane >> 4) << 4;
    const int b_rowi = (lane & 7) + ((lane >> 4) << 3);
    const int b_colx = ((lane >> 3) & 1) << 4;

    for (int c = 0; c < 16; c++) {
        CP_WAIT(0);                            // x/W for chunk c+1 arrived
        __syncthreads();                       // convert(c) + loads visible
        if (c + 2 < 16) load_stage(c + 2);     // xbuf[c&1] free (converted)

        const uint32_t apc = sb + APAN_OFF + (c & 1) * 16384;
        const uint32_t sW  = sb + WBUF_OFF + (c % 3) * 32768;
        const uint32_t xsn = sb + ((c + 1) & 1) * XBUF_B;
        const uint32_t apn = sb + APAN_OFF + ((c + 1) & 1) * 16384;
        const bool do_cvt = (c + 1 < 16);

#pragma unroll
        for (int ks = 0; ks < 4; ks++) {
            if (do_cvt) convert_quarter(xsn, apn, tid, ks);
            uint32_t bw[4][4];
            const int bcol = ks * 32 + b_colx;
#pragma unroll
            for (int g = 0; g < 4; g++) {
                const uint32_t off =
                    SW128((uint32_t)((warp_n + g * 16 + b_rowi) * 128 + bcol));
                ldsm4(bw[g][0], bw[g][1], bw[g][2], bw[g][3], sW + off);
            }
            const int acol = ks * 32 + a_colx;
#pragma unroll
            for (int mt = 0; mt < 4; mt++) {
                uint32_t a[4];
                const uint32_t off = SW128((uint32_t)((a_row + mt * 16) * 128 + acol));
                ldsm4(a[0], a[1], a[2], a[3], apc + off);
#pragma unroll
                for (int nt = 0; nt < 8; nt++)
                    mma16816(acc[mt][nt], a, &bw[nt >> 1][(nt & 1) * 2]);
            }
        }
    }

    const int qr = lane >> 2;
    const int qc = (lane & 3) * 2;
#pragma unroll
    for (int mt = 0; mt < 4; mt++) {
        const int m = m0 + warp_m + mt * 16 + qr;
#pragma unroll
        for (int nt = 0; nt < 8; nt++) {
            const int n = ncol0 + warp_n + nt * 8 + qc;
            const float b0 = bias[n], b1 = bias[n + 1];
            float* C = acc[mt][nt];
            *(uint32_t*)&Y[(size_t)m * CDIM + n] = packh2(C[0] + b0, C[1] + b1);
            *(uint32_t*)&Y[(size_t)(m + 8) * CDIM + n] = packh2(C[2] + b0, C[3] + b1);
        }
    }
}

// ---------------------------------------------------------------------------
// Out-proj GEMM (R13 form): A = fp16 attn output, 3-stage cp.async, direct
// fp32 transposed stores (R14 staging reverted).
// ---------------------------------------------------------------------------
#define OP_STAGE 49152              // A 16K | W 32K
#define OP_SMEM (3 * OP_STAGE)      // 144 KB

__global__ __launch_bounds__(256, 1)
void gemm_oproj(const __half* __restrict__ Af, const __half* __restrict__ Wf,
                const float* __restrict__ bo, float* __restrict__ Y)
{
    extern __shared__ char smem[];
    const uint32_t sb = smem_u32(smem);
    const int tid = threadIdx.x;
    const int wid = tid >> 5, lane = tid & 31;
    const int m0 = blockIdx.y * 128;
    const int ncol0 = blockIdx.x * 256;

    const __half* Bw = Wf + ((size_t)3 * CDIM + ncol0) * CDIM;
    const __half* Ah = Af + (size_t)m0 * CDIM;

    const int warp_m = (wid & 1) * 64;
    const int warp_n = (wid >> 1) * 64;

    float acc[4][8][4];
#pragma unroll
    for (int i = 0; i < 4; i++)
#pragma unroll
        for (int j = 0; j < 8; j++)
#pragma unroll
            for (int r = 0; r < 4; r++) acc[i][j][r] = 0.0f;

    auto load_stage = [&](int chunk) {
        const uint32_t st = sb + (chunk % 3) * OP_STAGE;
        const int kk = chunk * 64;
#pragma unroll
        for (int i = 0; i < 4; i++) {
            const int idx = tid + i * 256;
            const int r = idx >> 3, cc = idx & 7;
            const uint32_t sw = SW128((uint32_t)(r * 128 + cc * 16));
            CP_ASYNC16(st + sw, (const char*)(Ah + (size_t)r * CDIM + kk) + cc * 16);
        }
#pragma unroll
        for (int i = 0; i < 8; i++) {
            const int idx = tid + i * 256;
            const int r = idx >> 3, cc = idx & 7;
            const uint32_t sw = SW128((uint32_t)(r * 128 + cc * 16));
            CP_ASYNC16(st + 16384 + sw, (const char*)(Bw + (size_t)r * CDIM + kk) + cc * 16);
        }
        CP_COMMIT();
    };

    load_stage(0);
    load_stage(1);

    const int a_row = warp_m + (lane & 15);
    const int a_colx = (lane >> 4) << 4;
    const int b_rowi = (lane & 7) + ((lane >> 4) << 3);
    const int b_colx = ((lane >> 3) & 1) << 4;

    for (int c = 0; c < 16; c++) {
        if (c < 15) CP_WAIT(1); else CP_WAIT(0);
        __syncthreads();
        if (c + 2 < 16) load_stage(c + 2);

        const uint32_t sA = sb + (c % 3) * OP_STAGE;
        const uint32_t sW = sA + 16384;

#pragma unroll
        for (int ks = 0; ks < 4; ks++) {
            uint32_t bw[4][4];
            const int bcol = ks * 32 + b_colx;
#pragma unroll
            for (int g = 0; g < 4; g++) {
                const uint32_t off =
                    SW128((uint32_t)((warp_n + g * 16 + b_rowi) * 128 + bcol));
                ldsm4(bw[g][0], bw[g][1], bw[g][2], bw[g][3], sW + off);
            }
            const int acol = ks * 32 + a_colx;
#pragma unroll
            for (int mt = 0; mt < 4; mt++) {
                uint32_t a[4];
                const uint32_t off = SW128((uint32_t)((a_row + mt * 16) * 128 + acol));
                ldsm4(a[0], a[1], a[2], a[3], sA + off);
#pragma unroll
                for (int nt = 0; nt < 8; nt++)
                    mma16816(acc[mt][nt], a, &bw[nt >> 1][(nt & 1) * 2]);
            }
        }
    }

    const int qr = lane >> 2;
    const int qc = (lane & 3) * 2;
#pragma unroll
    for (int mt = 0; mt < 4; mt++) {
        const int m = m0 + warp_m + mt * 16 + qr;
#pragma unroll
        for (int nt = 0; nt < 8; nt++) {
            const int n = ncol0 + warp_n + nt * 8 + qc;
            const float b0 = bo[n], b1 = bo[n + 1];
            float* C = acc[mt][nt];
            const int bb = m >> 12, l = m & (LDIM - 1);
            float* Y0 = Y + ((size_t)(bb * CDIM) + n) * LDIM;
            Y0[l]            = C[0] + b0;
            Y0[LDIM + l]     = C[1] + b1;
            Y0[l + 8]        = C[2] + b0;
            Y0[LDIM + l + 8] = C[3] + b1;
        }
    }
}

// ---------------------------------------------------------------------------
// Tensor-core attention (unchanged from R12): one CTA (128 thr) per (b,n,h).
// ---------------------------------------------------------------------------
#define ATT_SMEM 49152              // Q|K|V tiles, 16KB each

__global__ __launch_bounds__(128, 3)
void attn_tc(const __half* __restrict__ Qg, const __half* __restrict__ Kg,
             const __half* __restrict__ Vg, __half* __restrict__ Of)
{
    extern __shared__ char smx[];
    const uint32_t sb = smem_u32(smx);
    const int tid = threadIdx.x, lane = tid & 31, wid = tid >> 5;
    const int n = blockIdx.x, h = blockIdx.y, b = blockIdx.z;
    const size_t base = ((size_t)b * LDIM + (size_t)n * CHUNK) * CDIM + (size_t)h * HD;

#pragma unroll
    for (int i = 0; i < 8; i++) {
        const int idx = tid + i * 128;
        const int row = idx >> 4, c8 = idx & 15;
        const uint32_t soff = (uint32_t)((c8 >> 3) * 8192 +
                                         SW128(row * 128 + (c8 & 7) * 16));
        const size_t g = base + (size_t)row * CDIM + c8 * 8;
        CP_ASYNC16(sb + soff,         Qg + g);
        CP_ASYNC16(sb + 16384 + soff, Kg + g);
        CP_ASYNC16(sb + 32768 + soff, Vg + g);
    }
    CP_COMMIT();
    CP_WAIT(0);
    __syncthreads();

    const int warp_m = wid * 16;
    const int a_row  = warp_m + (lane & 15);
    const int a_colx = (lane >> 4) << 4;
    const int b_rowi = (lane & 7) + ((lane >> 4) << 3);
    const int b_colx = ((lane >> 3) & 1) << 4;

    float sacc[8][4];
#pragma unroll
    for (int i = 0; i < 8; i++)
#pragma unroll
        for (int r = 0; r < 4; r++) sacc[i][r] = 0.0f;

#pragma unroll
    for (int ks = 0; ks < 8; ks++) {
        const uint32_t pan = (ks >> 2) * 8192;
        const int kp = (ks & 3) * 32;
        uint32_t a[4];
        ldsm4(a[0], a[1], a[2], a[3],
              sb + pan + SW128((uint32_t)(a_row * 128 + kp + a_colx)));
        uint32_t bw[4][4];
#pragma unroll
        for (int g = 0; g < 4; g++)
            ldsm4(bw[g][0], bw[g][1], bw[g][2], bw[g][3],
                  sb + 16384 + pan +
                  SW128((uint32_t)((g * 16 + b_rowi) * 128 + kp + b_colx)));
#pragma unroll
        for (int nt = 0; nt < 8; nt++)
            mma16816(sacc[nt], a, &bw[nt >> 1][(nt & 1) * 2]);
    }

    {
        const float scale = 0.08838834764831845f;   // 1/sqrt(128)
        float m0 = -1e30f, m1 = -1e30f;
#pragma unroll
        for (int nt = 0; nt < 8; nt++) {
#pragma unroll
            for (int r = 0; r < 4; r++) sacc[nt][r] *= scale;
            m0 = fmaxf(m0, fmaxf(sacc[nt][0], sacc[nt][1]));
            m1 = fmaxf(m1, fmaxf(sacc[nt][2], sacc[nt][3]));
        }
        m0 = fmaxf(m0, __shfl_xor_sync(0xffffffffu, m0, 1));
        m0 = fmaxf(m0, __shfl_xor_sync(0xffffffffu, m0, 2));
        m1 = fmaxf(m1, __shfl_xor_sync(0xffffffffu, m1, 1));
        m1 = fmaxf(m1, __shfl_xor_sync(0xffffffffu, m1, 2));
        float s0 = 0.0f, s1 = 0.0f;
#pragma unroll
        for (int nt = 0; nt < 8; nt++) {
            sacc[nt][0] = __expf(sacc[nt][0] - m0); s0 += sacc[nt][0];
            sacc[nt][1] = __expf(sacc[nt][1] - m0); s0 += sacc[nt][1];
            sacc[nt][2] = __expf(sacc[nt][2] - m1); s1 += sacc[nt][2];
            sacc[nt][3] = __expf(sacc[nt][3] - m1); s1 += sacc[nt][3];
        }
        s0 += __shfl_xor_sync(0xffffffffu, s0, 1);
        s0 += __shfl_xor_sync(0xffffffffu, s0, 2);
        s1 += __shfl_xor_sync(0xffffffffu, s1, 1);
        s1 += __shfl_xor_sync(0xffffffffu, s1, 2);
        const float i0 = 1.0f / s0, i1 = 1.0f / s1;
#pragma unroll
        for (int nt = 0; nt < 8; nt++) {
            sacc[nt][0] *= i0; sacc[nt][1] *= i0;
            sacc[nt][2] *= i1; sacc[nt][3] *= i1;
        }
    }

    __syncthreads();

    float oacc[16][4];
#pragma unroll
    for (int i = 0; i < 16; i++)
#pragma unroll
        for (int r = 0; r < 4; r++) oacc[i][r] = 0.0f;

    const int lg = lane >> 3, li = lane & 7;
#pragma unroll
    for (int ks2 = 0; ks2 < 4; ks2++) {
        const int t0 = 2 * ks2, t1 = t0 + 1;
        uint32_t af[4];
        af[0] = packh2(sacc[t0][0], sacc[t0][1]);
        af[1] = packh2(sacc[t0][2], sacc[t0][3]);
        af[2] = packh2(sacc[t1][0], sacc[t1][1]);
        af[3] = packh2(sacc[t1][2], sacc[t1][3]);
        const int krow = ks2 * 16 + (lg & 1) * 8 + li;
#pragma unroll
        for (int j = 0; j < 8; j++) {
            const int n0 = j * 16;
            const uint32_t pan = (uint32_t)((n0 >> 6) * 8192);
            const int ncol = (n0 & 63) + (lg >> 1) * 8;
            uint32_t r0, r1, r2, r3;
            ldsm4t(r0, r1, r2, r3,
                   sb + 32768 + pan + SW128((uint32_t)(krow * 128 + ncol * 2)));
            uint32_t b01[2] = {r0, r1}, b23[2] = {r2, r3};
            mma16816(oacc[2 * j],     af, b01);
            mma16816(oacc[2 * j + 1], af, b23);
        }
    }

    {
        const int r0 = warp_m + (lane >> 2);
        const int cb = (lane & 3) * 4;
#pragma unroll
        for (int nt = 0; nt < 16; nt++) {
            *(uint32_t*)(smx + r0 * 272 + nt * 16 + cb) =
                packh2(oacc[nt][0], oacc[nt][1]);
            *(uint32_t*)(smx + (r0 + 8) * 272 + nt * 16 + cb) =
                packh2(oacc[nt][2], oacc[nt][3]);
        }
    }
    __syncthreads();
#pragma unroll
    for (int i = 0; i < 8; i++) {
        const int idx = tid + i * 128;
        const int row = idx >> 4, c16 = idx & 15;
        uint4 v = *(uint4*)(smx + row * 272 + c16 * 16);
        *(uint4*)&Of[base + (size_t)row * CDIM + c16 * 8] = v;
    }
}

// ---------------------------------------------------------------------------
extern "C" void kernel_launch(void* const* d_in, const int* in_sizes, int n_in,
                              void* d_out, int out_size)
{
    const float* x  = (const float*)d_in[0];
    const float* Wq = (const float*)d_in[1];
    const float* bq = (const float*)d_in[2];
    const float* Wk = (const float*)d_in[3];
    const float* bk = (const float*)d_in[4];
    const float* Wv = (const float*)d_in[5];
    const float* bv = (const float*)d_in[6];
    const float* Wo = (const float*)d_in[7];
    const float* bo = (const float*)d_in[8];
    float* out = (float*)d_out;

    __half *Qh, *Kh, *Vh, *Af, *Wf;
    cudaGetSymbolAddress((void**)&Qh, g_Qh);
    cudaGetSymbolAddress((void**)&Kh, g_Kh);
    cudaGetSymbolAddress((void**)&Vh, g_Vh);
    cudaGetSymbolAddress((void**)&Af, g_Af);
    cudaGetSymbolAddress((void**)&Wf, g_Wf);

    cudaFuncSetAttribute(attn_tc, cudaFuncAttributeMaxDynamicSharedMemorySize, ATT_SMEM);
    cudaFuncSetAttribute(gemm_qkv, cudaFuncAttributeMaxDynamicSharedMemorySize, QKV_SMEM);
    cudaFuncSetAttribute(gemm_oproj, cudaFuncAttributeMaxDynamicSharedMemorySize, OP_SMEM);

    // 1) weight conversion only (x conversion is fused into gemm_qkv)
    convert_w<<<dim3(CDIM / 32, CDIM / 32, 4), dim3(32, 8)>>>(Wq, Wk, Wv, Wo, Wf);

    // 2) fused convert+QKV projection -> fp16 Q,K,V (grid: nt fast, m slow)
    gemm_qkv<<<dim3(12, MTOT / 128), 256, QKV_SMEM>>>(
        x, Wf, bq, bk, bv, Qh, Kh, Vh);

    // 3) tensor-core block-diagonal attention -> fp16 O
    attn_tc<<<dim3(NCHUNK, HEADS, BDIM), 128, ATT_SMEM>>>(Qh, Kh, Vh, Af);

    // 4) output projection (direct fp32 transposed stores to [B,C,L])
    gemm_oproj<<<dim3(4, MTOT / 128), 256, OP_SMEM>>>(Af, Wf, bo, out);
}

// round 16
// speedup vs baseline: 1.3018x; 1.3018x over previous
#include <cuda_runtime.h>
#include <cuda_fp16.h>
#include <cstdint>
#include <math.h>

// ---------------------------------------------------------------------------
// ChunkedAttention: B=8, C=1024, L=4096, H=8, hd=128, CHUNK=64, nc=64
// Round 16: R13 structure (separate convert_x, direct stores), GEMM retiled
// to CTA 128x128 / warp 64x32 / <=128 regs -> 2 CTAs/SM to fill pipeline
// bubbles (R15 ncu: tensor 62%, occ 12%, 1 CTA/SM). Numerics = R13.
// ---------------------------------------------------------------------------

#define BDIM 8
#define CDIM 1024
#define LDIM 4096
#define HEADS 8
#define HD 128
#define CHUNK 64
#define NCHUNK (LDIM / CHUNK)
#define MTOT (BDIM * LDIM)          // 32768 rows

__device__ __half g_Qh[(size_t)MTOT * CDIM];
__device__ __half g_Kh[(size_t)MTOT * CDIM];
__device__ __half g_Vh[(size_t)MTOT * CDIM];
__device__ __half g_Af[(size_t)MTOT * CDIM];            // GEMM A / attn out
__device__ __half g_Wf[(size_t)4 * CDIM * CDIM];        // [mat][co][c] fp16

// ------------------------------ PTX helpers --------------------------------
__device__ __forceinline__ uint32_t smem_u32(const void* p) {
    uint32_t a;
    asm("{ .reg .u64 t; cvta.to.shared.u64 t, %1; cvt.u32.u64 %0, t; }"
        : "=r"(a) : "l"(p));
    return a;
}
#define CP_ASYNC16(dst, src) \
    asm volatile("cp.async.cg.shared.global [%0], [%1], 16;" :: "r"(dst), "l"(src))
#define CP_COMMIT() asm volatile("cp.async.commit_group;" ::: "memory")
#define CP_WAIT(n)  asm volatile("cp.async.wait_group %0;" :: "n"(n) : "memory")
#define SW128(off) ((off) ^ (((off) >> 3) & 0x70))

__device__ __forceinline__ void ldsm4(uint32_t& r0, uint32_t& r1,
                                      uint32_t& r2, uint32_t& r3, uint32_t a) {
    asm volatile("ldmatrix.sync.aligned.m8n8.x4.shared.b16 {%0,%1,%2,%3}, [%4];"
                 : "=r"(r0), "=r"(r1), "=r"(r2), "=r"(r3) : "r"(a));
}
__device__ __forceinline__ void ldsm4t(uint32_t& r0, uint32_t& r1,
                                       uint32_t& r2, uint32_t& r3, uint32_t a) {
    asm volatile("ldmatrix.sync.aligned.m8n8.x4.trans.shared.b16 {%0,%1,%2,%3}, [%4];"
                 : "=r"(r0), "=r"(r1), "=r"(r2), "=r"(r3) : "r"(a));
}
__device__ __forceinline__ void mma16816(float* c, const uint32_t* a,
                                         const uint32_t* b) {
    asm volatile(
        "mma.sync.aligned.m16n8k16.row.col.f32.f16.f16.f32 "
        "{%0,%1,%2,%3}, {%4,%5,%6,%7}, {%8,%9}, {%0,%1,%2,%3};"
        : "+f"(c[0]), "+f"(c[1]), "+f"(c[2]), "+f"(c[3])
        : "r"(a[0]), "r"(a[1]), "r"(a[2]), "r"(a[3]), "r"(b[0]), "r"(b[1]));
}
__device__ __forceinline__ uint32_t packh2(float x, float y) {
    __half2 h = __floats2half2_rn(x, y);
    return *(uint32_t*)&h;
}

// ---------------------------------------------------------------------------
// Conversions (R13 versions)
// ---------------------------------------------------------------------------
__global__ void convert_x(const float* __restrict__ x, __half* __restrict__ A) {
    __shared__ float t[32][33];
    const int b = blockIdx.z, l0 = blockIdx.x * 32, c0 = blockIdx.y * 32;
    const float* xb = x + ((size_t)b * CDIM + c0) * LDIM + l0;
#pragma unroll
    for (int i = 0; i < 32; i += 8)
        t[threadIdx.y + i][threadIdx.x] = xb[(size_t)(threadIdx.y + i) * LDIM + threadIdx.x];
    __syncthreads();
#pragma unroll
    for (int i = 0; i < 32; i += 8) {
        const int r = threadIdx.y + i;
        size_t o = ((size_t)b * LDIM + l0 + r) * CDIM + c0 + threadIdx.x;
        A[o] = __float2half(t[threadIdx.x][r]);
    }
}

__global__ void convert_w(const float* __restrict__ W0, const float* __restrict__ W1,
                          const float* __restrict__ W2, const float* __restrict__ W3,
                          __half* __restrict__ Wf) {
    __shared__ float t[32][33];
    const int z = blockIdx.z;
    const float* W = (z == 0) ? W0 : (z == 1) ? W1 : (z == 2) ? W2 : W3;
    const int c0 = blockIdx.x * 32, n0 = blockIdx.y * 32;
#pragma unroll
    for (int i = 0; i < 32; i += 8)
        t[threadIdx.y + i][threadIdx.x] = W[(size_t)(c0 + threadIdx.y + i) * CDIM + n0 + threadIdx.x];
    __syncthreads();
#pragma unroll
    for (int i = 0; i < 32; i += 8) {
        const int r = threadIdx.y + i;
        size_t o = ((size_t)z * CDIM + n0 + r) * CDIM + c0 + threadIdx.x;
        Wf[o] = __float2half(t[threadIdx.x][r]);
    }
}

// ---------------------------------------------------------------------------
// mma.sync GEMM (1 pass): Y[m, n] = sum_k A[m,k] * Wt[n,k] + bias[n]
// CTA 128x128, BK=64, 3-stage cp.async (one barrier/chunk), 8 warps (2x4),
// warp tile 64x32, acc=64 regs -> 2 CTAs/SM. Grid: x = nt (fast), y = m.
// MODE 0: fused QKV (grid.x=24: mat=x>>3, ncol0=(x&7)*128) -> fp16 stores.
// MODE 1: out-proj (grid.x=8) -> direct fp32 transposed stores.
// ---------------------------------------------------------------------------
#define STAGE_BYTES 32768           // A 16K | W 16K
#define GEMM_SMEM (3 * STAGE_BYTES) // 96 KB -> 2 CTAs/SM

template <int MODE>
__global__ __launch_bounds__(256, 2)
void gemm_mma(const __half* __restrict__ Af, const __half* __restrict__ Wf,
              const float* __restrict__ bq, const float* __restrict__ bk,
              const float* __restrict__ bv,
              void* __restrict__ Yq, void* __restrict__ Yk, void* __restrict__ Yv)
{
    extern __shared__ char smem[];
    const uint32_t sb = smem_u32(smem);
    const int tid = threadIdx.x;
    const int wid = tid >> 5, lane = tid & 31;
    const int m0 = blockIdx.y * 128;
    const int nt_blk = blockIdx.x;

    int mat, ncol0;
    const float* bias;
    void* Y;
    if (MODE == 0) {
        mat = nt_blk >> 3; ncol0 = (nt_blk & 7) * 128;
        bias = (mat == 0) ? bq : (mat == 1) ? bk : bv;
        Y = (mat == 0) ? Yq : (mat == 1) ? Yk : Yv;
    } else {
        mat = 3; ncol0 = nt_blk * 128; bias = bq; Y = Yq;
    }

    const __half* Bw = Wf + ((size_t)mat * CDIM + ncol0) * CDIM;
    const __half* Ah = Af + (size_t)m0 * CDIM;

    const int warp_m = (wid & 1) * 64;    // 0 or 64
    const int warp_n = (wid >> 1) * 32;   // 0,32,64,96

    float acc[4][4][4];
#pragma unroll
    for (int i = 0; i < 4; i++)
#pragma unroll
        for (int j = 0; j < 4; j++)
#pragma unroll
            for (int r = 0; r < 4; r++) acc[i][j][r] = 0.0f;

    auto load_stage = [&](int chunk) {
        const uint32_t st = sb + (chunk % 3) * STAGE_BYTES;
        const int kk = chunk * 64;
#pragma unroll
        for (int i = 0; i < 4; i++) {          // A: 128 rows x 8 x 16B
            const int idx = tid + i * 256;
            const int r = idx >> 3, c = idx & 7;
            const uint32_t sw = SW128((uint32_t)(r * 128 + c * 16));
            CP_ASYNC16(st + sw, (const char*)(Ah + (size_t)r * CDIM + kk) + c * 16);
        }
#pragma unroll
        for (int i = 0; i < 4; i++) {          // W: 128 rows x 8 x 16B
            const int idx = tid + i * 256;
            const int r = idx >> 3, c = idx & 7;
            const uint32_t sw = SW128((uint32_t)(r * 128 + c * 16));
            CP_ASYNC16(st + 16384 + sw, (const char*)(Bw + (size_t)r * CDIM + kk) + c * 16);
        }
        CP_COMMIT();
    };

    load_stage(0);
    load_stage(1);

    const int a_row = warp_m + (lane & 15);
    const int a_colx = (lane >> 4) << 4;
    const int b_rowi = (lane & 7) + ((lane >> 4) << 3);
    const int b_colx = ((lane >> 3) & 1) << 4;

    for (int c = 0; c < 16; c++) {
        if (c < 15) CP_WAIT(1); else CP_WAIT(0);
        __syncthreads();                       // sole barrier per chunk
        if (c + 2 < 16) load_stage(c + 2);

        const uint32_t sA = sb + (c % 3) * STAGE_BYTES;
        const uint32_t sW = sA + 16384;

#pragma unroll
        for (int ks = 0; ks < 4; ks++) {
            uint32_t bw[2][4];
            const int bcol = ks * 32 + b_colx;
#pragma unroll
            for (int g = 0; g < 2; g++) {
                const uint32_t off =
                    SW128((uint32_t)((warp_n + g * 16 + b_rowi) * 128 + bcol));
                ldsm4(bw[g][0], bw[g][1], bw[g][2], bw[g][3], sW + off);
            }
            const int acol = ks * 32 + a_colx;
#pragma unroll
            for (int mt = 0; mt < 4; mt++) {
                uint32_t a[4];
                const uint32_t off = SW128((uint32_t)((a_row + mt * 16) * 128 + acol));
                ldsm4(a[0], a[1], a[2], a[3], sA + off);
#pragma unroll
                for (int nt = 0; nt < 4; nt++)
                    mma16816(acc[mt][nt], a, &bw[nt >> 1][(nt & 1) * 2]);
            }
        }
    }

    const int qr = lane >> 2;
    const int qc = (lane & 3) * 2;
#pragma unroll
    for (int mt = 0; mt < 4; mt++) {
        const int m = m0 + warp_m + mt * 16 + qr;
#pragma unroll
        for (int nt = 0; nt < 4; nt++) {
            const int n = ncol0 + warp_n + nt * 8 + qc;
            const float b0 = bias[n], b1 = bias[n + 1];
            float* C = acc[mt][nt];
            if (MODE == 0) {
                __half* Yh = (__half*)Y;
                *(uint32_t*)&Yh[(size_t)m * CDIM + n] = packh2(C[0] + b0, C[1] + b1);
                *(uint32_t*)&Yh[(size_t)(m + 8) * CDIM + n] = packh2(C[2] + b0, C[3] + b1);
            } else {
                float* Yf = (float*)Y;
                const int bb = m >> 12, l = m & (LDIM - 1);
                float* Y0 = Yf + ((size_t)(bb * CDIM) + n) * LDIM;
                Y0[l]            = C[0] + b0;
                Y0[LDIM + l]     = C[1] + b1;
                Y0[l + 8]        = C[2] + b0;
                Y0[LDIM + l + 8] = C[3] + b1;
            }
        }
    }
}

// ---------------------------------------------------------------------------
// Tensor-core attention (unchanged from R12): one CTA (128 thr) per (b,n,h).
// ---------------------------------------------------------------------------
#define ATT_SMEM 49152              // Q|K|V tiles, 16KB each

__global__ __launch_bounds__(128, 3)
void attn_tc(const __half* __restrict__ Qg, const __half* __restrict__ Kg,
             const __half* __restrict__ Vg, __half* __restrict__ Of)
{
    extern __shared__ char smx[];
    const uint32_t sb = smem_u32(smx);
    const int tid = threadIdx.x, lane = tid & 31, wid = tid >> 5;
    const int n = blockIdx.x, h = blockIdx.y, b = blockIdx.z;
    const size_t base = ((size_t)b * LDIM + (size_t)n * CHUNK) * CDIM + (size_t)h * HD;

#pragma unroll
    for (int i = 0; i < 8; i++) {
        const int idx = tid + i * 128;
        const int row = idx >> 4, c8 = idx & 15;
        const uint32_t soff = (uint32_t)((c8 >> 3) * 8192 +
                                         SW128(row * 128 + (c8 & 7) * 16));
        const size_t g = base + (size_t)row * CDIM + c8 * 8;
        CP_ASYNC16(sb + soff,         Qg + g);
        CP_ASYNC16(sb + 16384 + soff, Kg + g);
        CP_ASYNC16(sb + 32768 + soff, Vg + g);
    }
    CP_COMMIT();
    CP_WAIT(0);
    __syncthreads();

    const int warp_m = wid * 16;
    const int a_row  = warp_m + (lane & 15);
    const int a_colx = (lane >> 4) << 4;
    const int b_rowi = (lane & 7) + ((lane >> 4) << 3);
    const int b_colx = ((lane >> 3) & 1) << 4;

    float sacc[8][4];
#pragma unroll
    for (int i = 0; i < 8; i++)
#pragma unroll
        for (int r = 0; r < 4; r++) sacc[i][r] = 0.0f;

#pragma unroll
    for (int ks = 0; ks < 8; ks++) {
        const uint32_t pan = (ks >> 2) * 8192;
        const int kp = (ks & 3) * 32;
        uint32_t a[4];
        ldsm4(a[0], a[1], a[2], a[3],
              sb + pan + SW128((uint32_t)(a_row * 128 + kp + a_colx)));
        uint32_t bw[4][4];
#pragma unroll
        for (int g = 0; g < 4; g++)
            ldsm4(bw[g][0], bw[g][1], bw[g][2], bw[g][3],
                  sb + 16384 + pan +
                  SW128((uint32_t)((g * 16 + b_rowi) * 128 + kp + b_colx)));
#pragma unroll
        for (int nt = 0; nt < 8; nt++)
            mma16816(sacc[nt], a, &bw[nt >> 1][(nt & 1) * 2]);
    }

    {
        const float scale = 0.08838834764831845f;   // 1/sqrt(128)
        float m0 = -1e30f, m1 = -1e30f;
#pragma unroll
        for (int nt = 0; nt < 8; nt++) {
#pragma unroll
            for (int r = 0; r < 4; r++) sacc[nt][r] *= scale;
            m0 = fmaxf(m0, fmaxf(sacc[nt][0], sacc[nt][1]));
            m1 = fmaxf(m1, fmaxf(sacc[nt][2], sacc[nt][3]));
        }
        m0 = fmaxf(m0, __shfl_xor_sync(0xffffffffu, m0, 1));
        m0 = fmaxf(m0, __shfl_xor_sync(0xffffffffu, m0, 2));
        m1 = fmaxf(m1, __shfl_xor_sync(0xffffffffu, m1, 1));
        m1 = fmaxf(m1, __shfl_xor_sync(0xffffffffu, m1, 2));
        float s0 = 0.0f, s1 = 0.0f;
#pragma unroll
        for (int nt = 0; nt < 8; nt++) {
            sacc[nt][0] = __expf(sacc[nt][0] - m0); s0 += sacc[nt][0];
            sacc[nt][1] = __expf(sacc[nt][1] - m0); s0 += sacc[nt][1];
            sacc[nt][2] = __expf(sacc[nt][2] - m1); s1 += sacc[nt][2];
            sacc[nt][3] = __expf(sacc[nt][3] - m1); s1 += sacc[nt][3];
        }
        s0 += __shfl_xor_sync(0xffffffffu, s0, 1);
        s0 += __shfl_xor_sync(0xffffffffu, s0, 2);
        s1 += __shfl_xor_sync(0xffffffffu, s1, 1);
        s1 += __shfl_xor_sync(0xffffffffu, s1, 2);
        const float i0 = 1.0f / s0, i1 = 1.0f / s1;
#pragma unroll
        for (int nt = 0; nt < 8; nt++) {
            sacc[nt][0] *= i0; sacc[nt][1] *= i0;
            sacc[nt][2] *= i1; sacc[nt][3] *= i1;
        }
    }

    __syncthreads();

    float oacc[16][4];
#pragma unroll
    for (int i = 0; i < 16; i++)
#pragma unroll
        for (int r = 0; r < 4; r++) oacc[i][r] = 0.0f;

    const int lg = lane >> 3, li = lane & 7;
#pragma unroll
    for (int ks2 = 0; ks2 < 4; ks2++) {
        const int t0 = 2 * ks2, t1 = t0 + 1;
        uint32_t af[4];
        af[0] = packh2(sacc[t0][0], sacc[t0][1]);
        af[1] = packh2(sacc[t0][2], sacc[t0][3]);
        af[2] = packh2(sacc[t1][0], sacc[t1][1]);
        af[3] = packh2(sacc[t1][2], sacc[t1][3]);
        const int krow = ks2 * 16 + (lg & 1) * 8 + li;
#pragma unroll
        for (int j = 0; j < 8; j++) {
            const int n0 = j * 16;
            const uint32_t pan = (uint32_t)((n0 >> 6) * 8192);
            const int ncol = (n0 & 63) + (lg >> 1) * 8;
            uint32_t r0, r1, r2, r3;
            ldsm4t(r0, r1, r2, r3,
                   sb + 32768 + pan + SW128((uint32_t)(krow * 128 + ncol * 2)));
            uint32_t b01[2] = {r0, r1}, b23[2] = {r2, r3};
            mma16816(oacc[2 * j],     af, b01);
            mma16816(oacc[2 * j + 1], af, b23);
        }
    }

    {
        const int r0 = warp_m + (lane >> 2);
        const int cb = (lane & 3) * 4;
#pragma unroll
        for (int nt = 0; nt < 16; nt++) {
            *(uint32_t*)(smx + r0 * 272 + nt * 16 + cb) =
                packh2(oacc[nt][0], oacc[nt][1]);
            *(uint32_t*)(smx + (r0 + 8) * 272 + nt * 16 + cb) =
                packh2(oacc[nt][2], oacc[nt][3]);
        }
    }
    __syncthreads();
#pragma unroll
    for (int i = 0; i < 8; i++) {
        const int idx = tid + i * 128;
        const int row = idx >> 4, c16 = idx & 15;
        uint4 v = *(uint4*)(smx + row * 272 + c16 * 16);
        *(uint4*)&Of[base + (size_t)row * CDIM + c16 * 8] = v;
    }
}

// ---------------------------------------------------------------------------
extern "C" void kernel_launch(void* const* d_in, const int* in_sizes, int n_in,
                              void* d_out, int out_size)
{
    const float* x  = (const float*)d_in[0];
    const float* Wq = (const float*)d_in[1];
    const float* bq = (const float*)d_in[2];
    const float* Wk = (const float*)d_in[3];
    const float* bk = (const float*)d_in[4];
    const float* Wv = (const float*)d_in[5];
    const float* bv = (const float*)d_in[6];
    const float* Wo = (const float*)d_in[7];
    const float* bo = (const float*)d_in[8];
    float* out = (float*)d_out;

    __half *Qh, *Kh, *Vh, *Af, *Wf;
    cudaGetSymbolAddress((void**)&Qh, g_Qh);
    cudaGetSymbolAddress((void**)&Kh, g_Kh);
    cudaGetSymbolAddress((void**)&Vh, g_Vh);
    cudaGetSymbolAddress((void**)&Af, g_Af);
    cudaGetSymbolAddress((void**)&Wf, g_Wf);

    cudaFuncSetAttribute(attn_tc, cudaFuncAttributeMaxDynamicSharedMemorySize, ATT_SMEM);
    cudaFuncSetAttribute(gemm_mma<0>, cudaFuncAttributeMaxDynamicSharedMemorySize, GEMM_SMEM);
    cudaFuncSetAttribute(gemm_mma<1>, cudaFuncAttributeMaxDynamicSharedMemorySize, GEMM_SMEM);

    // 1) conversions
    convert_w<<<dim3(CDIM / 32, CDIM / 32, 4), dim3(32, 8)>>>(Wq, Wk, Wv, Wo, Wf);
    convert_x<<<dim3(LDIM / 32, CDIM / 32, BDIM), dim3(32, 8)>>>(x, Af);

    // 2) fused QKV projection -> fp16 Q,K,V (grid: nt fast, m slow)
    gemm_mma<0><<<dim3(24, MTOT / 128), 256, GEMM_SMEM>>>(
        Af, Wf, bq, bk, bv, Qh, Kh, Vh);

    // 3) tensor-core block-diagonal attention -> fp16 O
    attn_tc<<<dim3(NCHUNK, HEADS, BDIM), 128, ATT_SMEM>>>(Qh, Kh, Vh, Af);

    // 4) output projection (direct fp32 transposed stores to [B,C,L])
    gemm_mma<1><<<dim3(8, MTOT / 128), 256, GEMM_SMEM>>>(
        Af, Wf, bo, bo, bo, out, out, out);
}